// round 11
// baseline (speedup 1.0000x reference)
#include <cuda_runtime.h>
#include <cuda_bf16.h>

// Problem constants (fixed by the reference)
#define BATCH   2
#define NPTS    8192
#define NTOT    (BATCH * NPTS)
#define DIM     32
#define R2      0.0009f     // 0.03^2
#define SIMT    0.7f
#define EPSN    1e-8f
#define MINLEAF 10

#define GRIDC   14                      // ceil(0.4 / 0.03)
#define NCELL   (GRIDC * GRIDC * GRIDC) // 2744
#define CAP     32                      // bucket capacity (mean occupancy ~1.5)
#define INVC    33.333332f              // 1 / 0.03
#define MARGIN  0.0302f                 // radius + safety margin for cell-range bound

#define TPB     256
#define NB      512                     // 1024 tiles / 512 blocks = exactly 2 each
#define LPP     16                      // lanes per point
#define PPQ     (TPB / LPP)             // 16 points per tile
#define FULL    0xffffffffu
#define PAD     36                      // smem row pad: 16B-aligned, conflict-safe

// Scratch (static __device__ — no allocations allowed)
__device__ float  g_en[NTOT * DIM];                  // normalized embeddings
__device__ int    g_cellcnt[BATCH * NCELL];
__device__ float4 g_bucket[BATCH * NCELL * CAP];     // (x,y,z, bitcast local idx)
__device__ int    g_leafcnt[BATCH];
__device__ int    g_bar_arrive;                      // zero-initialized
__device__ volatile int g_bar_gen;                   // monotonic epoch (never reset)

// Sense-reversal grid barrier. Safe: NB=512 <= 148 SMs x 4 co-resident blocks
// (regs<=64 via launch_bounds(256,4); smem ~19KB*4 << 228KB).
__device__ __forceinline__ void grid_barrier() {
    __syncthreads();
    if (threadIdx.x == 0) {
        int gen = g_bar_gen;
        __threadfence();
        if (atomicAdd(&g_bar_arrive, 1) == NB - 1) {
            atomicExch(&g_bar_arrive, 0);
            __threadfence();
            g_bar_gen = gen + 1;                     // release
        } else {
            while (g_bar_gen == gen) { __nanosleep(20); }
        }
        __threadfence();
    }
    __syncthreads();
}

// Candidate test — numerics identical to the rel_err==0.0 lineage.
__device__ __forceinline__ void test_cand(
    float4 p, float xi, float yi, float zi,
    const float* __restrict__ enp, const float* __restrict__ enb,
    const float* __restrict__ embb, float* __restrict__ accp,
    int& nbcnt, int& cnt)
{
    float dx = xi - p.x, dy = yi - p.y, dz = zi - p.z;
    float d2 = fmaf(dx, dx, fmaf(dy, dy, dz * dz));
    if (d2 < R2) {
        nbcnt++;
        int j = __float_as_int(p.w);
        const float4* ej = (const float4*)(enb + (size_t)j * DIM);
        float dot = 0.f;
#pragma unroll
        for (int q = 0; q < 8; q++) {
            float4 v = __ldg(ej + q);
            float4 u = *(const float4*)(enp + 4 * q);       // broadcast LDS.128
            dot = fmaf(v.x, u.x, dot); dot = fmaf(v.y, u.y, dot);
            dot = fmaf(v.z, u.z, dot); dot = fmaf(v.w, u.w, dot);
        }
        if (dot > SIMT) {                                   // rare: RAW embedding
            cnt++;
            const float4* rj = (const float4*)(embb + (size_t)j * DIM);
#pragma unroll
            for (int q = 0; q < 8; q++) {
                float4 v = __ldg(rj + q);
                atomicAdd(accp + 4*q,     v.x);
                atomicAdd(accp + 4*q + 1, v.y);
                atomicAdd(accp + 4*q + 2, v.z);
                atomicAdd(accp + 4*q + 3, v.w);
            }
        }
    }
}

__global__ void __launch_bounds__(TPB, 4)
fused_kernel(const float* __restrict__ points,
             const float* __restrict__ emb,
             const int*   __restrict__ leaf,
             const float* __restrict__ W1,
             const float* __restrict__ b1,
             const float* __restrict__ W2,
             const float* __restrict__ b2,
             float* __restrict__ out) {
    __shared__ __align__(16) float sW1[2 * DIM * DIM];   // 8 KB
    __shared__ __align__(16) float sW2[DIM * DIM];       // 4 KB
    __shared__ float sb1[DIM];
    __shared__ float sb2[DIM];
    __shared__ __align__(16) float s_en[PPQ * PAD];      // normalized emb of tile points
    __shared__ __align__(16) float s_ei[PPQ * PAD];      // raw emb of tile points
    __shared__ float s_acc[PPQ * PAD];                   // sim-sum accumulators

    const int tid = threadIdx.x;

    // ---- stage weights early (overlaps barrier waits) ----
    for (int t = tid; t < 2 * DIM * DIM; t += TPB) sW1[t] = W1[t];
    for (int t = tid; t < DIM * DIM; t += TPB)     sW2[t] = W2[t];
    if (tid < DIM) { sb1[tid] = b1[tid]; sb2[tid] = b2[tid]; }

    // ---- Phase Z: zero grid state ----
    {
        const int gtid = blockIdx.x * TPB + tid;
        if (gtid < BATCH * NCELL) g_cellcnt[gtid] = 0;
        if (gtid < BATCH)         g_leafcnt[gtid] = 0;
    }
    grid_barrier();

    // ---- Phase P: prep, 32 items per block (16384 = 512*32), 1 item/lane ----
    if (tid < 32) {
        const int idx = blockIdx.x * 32 + tid;           // warp 0 fully active
        const int b = idx / NPTS;                        // warp-homogeneous
        const int j = idx - b * NPTS;

        const float4* e4 = (const float4*)(emb + (size_t)idx * DIM);
        float v[DIM];
        float s = 0.f;
#pragma unroll
        for (int q = 0; q < 8; q++) {
            float4 t = __ldg(e4 + q);
            v[4*q+0] = t.x; v[4*q+1] = t.y; v[4*q+2] = t.z; v[4*q+3] = t.w;
            s = fmaf(t.x, t.x, s); s = fmaf(t.y, t.y, s);
            s = fmaf(t.z, t.z, s); s = fmaf(t.w, t.w, s);
        }
        float inv = 1.f / fmaxf(sqrtf(s), EPSN);
        float4* o4 = (float4*)(g_en + (size_t)idx * DIM);
#pragma unroll
        for (int q = 0; q < 8; q++)
            o4[q] = make_float4(v[4*q] * inv, v[4*q+1] * inv, v[4*q+2] * inv, v[4*q+3] * inv);

        int lf = leaf[idx] > 0;
        unsigned msk = __ballot_sync(FULL, lf);
        if (tid == 0 && msk)
            atomicAdd(&g_leafcnt[b], __popc(msk));

        if (lf) {
            float x = points[3 * (size_t)idx];
            float y = points[3 * (size_t)idx + 1];
            float z = points[3 * (size_t)idx + 2];
            int cx = min(GRIDC - 1, (int)(x * INVC));
            int cy = min(GRIDC - 1, (int)(y * INVC));
            int cz = min(GRIDC - 1, (int)(z * INVC));
            int c = b * NCELL + (cz * GRIDC + cy) * GRIDC + cx;
            int pos = atomicAdd(&g_cellcnt[c], 1);
            if (pos < CAP)
                g_bucket[(size_t)c * CAP + pos] = make_float4(x, y, z, __int_as_float(j));
        }
    }
    grid_barrier();

    // ---- Phase Q: 16 lanes/point, 16 points/tile, exactly 2 tiles/block ----
    const int lc0 = g_leafcnt[0], lc1 = g_leafcnt[1];
    const int pt = tid >> 4;            // 0..15  local point
    const int ln = tid & 15;            // 0..15  lane within point group
    const unsigned gmask = 0xFFFFu << (tid & 16);    // this group's 16 lanes
    const float* en_i = s_en + pt * PAD;
    float* accp = s_acc + pt * PAD;

#pragma unroll
    for (int w = 0; w < 2; w++) {
        const int tile = blockIdx.x + w * NB;
        const int gi0 = tile * PPQ;
        const int b = gi0 >> 13;                         // / NPTS, tile-uniform

        // cooperative stage: tile embeddings (raw + normalized), zero accumulators
        for (int t = tid; t < PPQ * DIM; t += TPB) {
            int p = t >> 5, k = t & 31;
            s_ei[p * PAD + k]  = __ldg(emb + ((size_t)gi0 + p) * DIM + k);
            s_en[p * PAD + k]  = g_en[((size_t)gi0 + p) * DIM + k];
            s_acc[p * PAD + k] = 0.f;
        }
        __syncthreads();

        const int gi = gi0 + pt;
        const float xi = __ldg(points + 3 * (size_t)gi);
        const float yi = __ldg(points + 3 * (size_t)gi + 1);
        const float zi = __ldg(points + 3 * (size_t)gi + 2);

        const int cx0 = max(0, (int)((xi - MARGIN) * INVC)), cx1 = min(GRIDC - 1, (int)((xi + MARGIN) * INVC));
        const int cy0 = max(0, (int)((yi - MARGIN) * INVC)), cy1 = min(GRIDC - 1, (int)((yi + MARGIN) * INVC));
        const int cz0 = max(0, (int)((zi - MARGIN) * INVC)), cz1 = min(GRIDC - 1, (int)((zi + MARGIN) * INVC));
        const int nx = cx1 - cx0 + 1, ny = cy1 - cy0 + 1, nz = cz1 - cz0 + 1;
        const int nxy = nx * ny, ncn = nxy * nz;         // <= 64
        const float invnxy = 1.f / (float)nxy;
        const float invnx  = 1.f / (float)nx;

        int nbcnt = 0, cnt = 0;
        const float* enb  = g_en + (size_t)b * NPTS * DIM;
        const float* embb = emb  + (size_t)b * NPTS * DIM;
        const int*   cntb = g_cellcnt + b * NCELL;

        // ---- pipelined scan: decode all owned cells, then launch ALL count
        //      loads + ALL first-slot loads before consuming any of them ----
        int nv[4];
        const float4* bk[4];
#pragma unroll
        for (int s = 0; s < 4; s++) {
            int cc = ln + s * LPP;
            int cell = 0;
            bool valid = cc < ncn;
            if (valid) {
                // division-free decode: exact for cc<64
                int cz = (int)(((float)cc + 0.5f) * invnxy);
                int r  = cc - cz * nxy;
                int cy = (int)(((float)r + 0.5f) * invnx);
                int cx = r - cy * nx;
                cell = ((cz0 + cz) * GRIDC + (cy0 + cy)) * GRIDC + (cx0 + cx);
            }
            nv[s] = valid ? __ldg(cntb + cell) : 0;      // independent L2 loads
            bk[s] = g_bucket + ((size_t)b * NCELL + cell) * CAP;
        }
        // first slot of every owned cell: unconditional (cell 0 safe), in flight together
        float4 pre0 = __ldg(bk[0]);
        float4 pre1 = __ldg(bk[1]);
        float4 pre2 = __ldg(bk[2]);
        float4 pre3 = __ldg(bk[3]);

#pragma unroll
        for (int s = 0; s < 4; s++) {
            int n = min(nv[s], CAP);
            if (n > 0) {
                float4 p0 = (s == 0) ? pre0 : (s == 1) ? pre1 : (s == 2) ? pre2 : pre3;
                test_cand(p0, xi, yi, zi, en_i, enb, embb, accp, nbcnt, cnt);
                for (int k = 1; k < n; k++) {
                    float4 p = __ldg(bk[s] + k);
                    test_cand(p, xi, yi, zi, en_i, enb, embb, accp, nbcnt, cnt);
                }
            }
        }

        // 16-lane butterfly reduce (xor d<16 stays within group)
#pragma unroll
        for (int d = 1; d < LPP; d <<= 1) {
            nbcnt += __shfl_xor_sync(FULL, nbcnt, d);
            cnt   += __shfl_xor_sync(FULL, cnt, d);
        }
        __syncwarp();                                    // group smem atomics visible

        const bool cond = (__ldg(leaf + gi) > 0) && (nbcnt > 1) && (cnt > 0)
                       && ((b == 0 ? lc0 : lc1) >= MINLEAF);

        const int ob = ln * 2;
        if (cond) {                                      // group-uniform branch
            const float rinv = 1.f / (float)cnt;         // cnt>0 here: == max(cnt,1)

            float h0 = sb1[ob], h1 = sb1[ob + 1];
#pragma unroll 8
            for (int k = 0; k < DIM; k++) {
                float c = s_ei[pt * PAD + k];
                float2 wv = *(const float2*)(sW1 + k * DIM + ob);
                h0 = fmaf(c, wv.x, h0); h1 = fmaf(c, wv.y, h1);
            }
#pragma unroll 8
            for (int k = 0; k < DIM; k++) {
                float c = accp[k] * rinv;
                float2 wv = *(const float2*)(sW1 + (DIM + k) * DIM + ob);
                h0 = fmaf(c, wv.x, h0); h1 = fmaf(c, wv.y, h1);
            }
            h0 = fmaxf(h0, 0.f); h1 = fmaxf(h1, 0.f);

            // layer 2: h broadcast via width-16 shfl (group-converged: cond uniform)
            float o0 = sb2[ob], o1 = sb2[ob + 1];
#pragma unroll 8
            for (int k16 = 0; k16 < 16; k16++) {
                float c0 = __shfl_sync(gmask, h0, k16, 16);   // h[2*k16]
                float c1 = __shfl_sync(gmask, h1, k16, 16);   // h[2*k16+1]
                float2 w0 = *(const float2*)(sW2 + (2 * k16) * DIM + ob);
                o0 = fmaf(c0, w0.x, o0); o1 = fmaf(c0, w0.y, o1);
                float2 w1 = *(const float2*)(sW2 + (2 * k16 + 1) * DIM + ob);
                o0 = fmaf(c1, w1.x, o0); o1 = fmaf(c1, w1.y, o1);
            }
            *(float2*)(out + (size_t)gi * DIM + ob) = make_float2(o0, o1);
        } else {
            float2 r = *(const float2*)(s_ei + pt * PAD + ob);   // passthrough
            *(float2*)(out + (size_t)gi * DIM + ob) = r;
        }
        __syncthreads();                                 // before next tile restage
    }
}

extern "C" void kernel_launch(void* const* d_in, const int* in_sizes, int n_in,
                              void* d_out, int out_size) {
    const float* points = (const float*)d_in[0];
    const float* emb    = (const float*)d_in[1];
    const int*   leaf   = (const int*)d_in[2];
    const float* W1     = (const float*)d_in[3];
    const float* b1     = (const float*)d_in[4];
    const float* W2     = (const float*)d_in[5];
    const float* b2     = (const float*)d_in[6];
    float* out = (float*)d_out;

    fused_kernel<<<NB, TPB>>>(points, emb, leaf, W1, b1, W2, b2, out);
}

// round 12
// speedup vs baseline: 1.6153x; 1.6153x over previous
#include <cuda_runtime.h>
#include <cuda_bf16.h>

// Problem constants (fixed by the reference)
#define BATCH   2
#define NPTS    8192
#define NTOT    (BATCH * NPTS)
#define DIM     32
#define R2      0.0009f     // 0.03^2
#define SIMT    0.7f
#define EPSN    1e-8f
#define MINLEAF 10

#define GRIDC   14                      // ceil(0.4 / 0.03)
#define NCELL   (GRIDC * GRIDC * GRIDC) // 2744
#define CAP     32                      // bucket capacity (mean occupancy ~1.5)
#define INVC    33.333332f              // 1 / 0.03
#define MARGIN  0.0302f                 // radius + safety margin for cell-range bound

#define TPB     256
#define NB      512                     // 1024 tiles / 512 blocks = exactly 2 each
#define LPP     16                      // lanes per point
#define PPQ     (TPB / LPP)             // 16 points per tile
#define FULL    0xffffffffu
#define PAD     36                      // smem row pad: 16B-aligned, conflict-safe
#define LCAP    32                      // per-point sim-pass list capacity (observed cnt ~1-3)

// Scratch (static __device__ — no allocations allowed)
__device__ float  g_en[NTOT * DIM];                  // normalized embeddings
__device__ int    g_cellcnt[BATCH * NCELL];
__device__ float4 g_bucket[BATCH * NCELL * CAP];     // (x,y,z, bitcast local idx)
__device__ int    g_leafcnt[BATCH];
__device__ int    g_bar_arrive;                      // zero-initialized
__device__ volatile int g_bar_gen;                   // monotonic epoch (never reset)

// Sense-reversal grid barrier. Safe: NB=512 <= 148 SMs x 4 co-resident blocks
// (regs<=64 via launch_bounds(256,4); smem ~41KB*4 <= 228KB).
__device__ __forceinline__ void grid_barrier() {
    __syncthreads();
    if (threadIdx.x == 0) {
        int gen = g_bar_gen;
        __threadfence();
        if (atomicAdd(&g_bar_arrive, 1) == NB - 1) {
            atomicExch(&g_bar_arrive, 0);
            __threadfence();
            g_bar_gen = gen + 1;                     // release
        } else {
            while (g_bar_gen == gen) { __nanosleep(20); }
        }
        __threadfence();
    }
    __syncthreads();
}

__global__ void __launch_bounds__(TPB, 4)
fused_kernel(const float* __restrict__ points,
             const float* __restrict__ emb,
             const int*   __restrict__ leaf,
             const float* __restrict__ W1,
             const float* __restrict__ b1,
             const float* __restrict__ W2,
             const float* __restrict__ b2,
             float* __restrict__ out) {
    __shared__ __align__(16) float sW1[2 * DIM * DIM];   // 8 KB
    __shared__ __align__(16) float sW2[DIM * DIM];       // 4 KB
    __shared__ float sb1[DIM];
    __shared__ float sb2[DIM];
    __shared__ int   s_cnt[BATCH * NCELL];               // 21.4 KB (both batches)
    __shared__ __align__(16) float s_en[PPQ * PAD];      // normalized emb of tile points
    __shared__ __align__(16) float s_ei[PPQ * PAD];      // raw emb of tile points
    __shared__ int   s_list[PPQ * LCAP];                 // deferred sim-pass j lists
    __shared__ int   s_lcnt[PPQ];                        // list counters

    const int tid = threadIdx.x;

    // ---- Phase Z: zero grid state ----
    {
        const int gtid = blockIdx.x * TPB + tid;
        if (gtid < BATCH * NCELL) g_cellcnt[gtid] = 0;
        if (gtid < BATCH)         g_leafcnt[gtid] = 0;
    }
    grid_barrier();

    // ---- Phase P: prep, 32 items per block (16384 = 512*32), 1 item/lane ----
    if (tid < 32) {
        const int idx = blockIdx.x * 32 + tid;           // warp 0 fully active
        const int b = idx / NPTS;                        // warp-homogeneous
        const int j = idx - b * NPTS;

        const float4* e4 = (const float4*)(emb + (size_t)idx * DIM);
        float v[DIM];
        float s = 0.f;
#pragma unroll
        for (int q = 0; q < 8; q++) {
            float4 t = __ldg(e4 + q);
            v[4*q+0] = t.x; v[4*q+1] = t.y; v[4*q+2] = t.z; v[4*q+3] = t.w;
            s = fmaf(t.x, t.x, s); s = fmaf(t.y, t.y, s);
            s = fmaf(t.z, t.z, s); s = fmaf(t.w, t.w, s);
        }
        float inv = 1.f / fmaxf(sqrtf(s), EPSN);
        float4* o4 = (float4*)(g_en + (size_t)idx * DIM);
#pragma unroll
        for (int q = 0; q < 8; q++)
            o4[q] = make_float4(v[4*q] * inv, v[4*q+1] * inv, v[4*q+2] * inv, v[4*q+3] * inv);

        int lf = leaf[idx] > 0;
        unsigned msk = __ballot_sync(FULL, lf);
        if (tid == 0 && msk)
            atomicAdd(&g_leafcnt[b], __popc(msk));

        if (lf) {
            float x = points[3 * (size_t)idx];
            float y = points[3 * (size_t)idx + 1];
            float z = points[3 * (size_t)idx + 2];
            int cx = min(GRIDC - 1, (int)(x * INVC));
            int cy = min(GRIDC - 1, (int)(y * INVC));
            int cz = min(GRIDC - 1, (int)(z * INVC));
            int c = b * NCELL + (cz * GRIDC + cy) * GRIDC + cx;
            int pos = atomicAdd(&g_cellcnt[c], 1);
            if (pos < CAP)
                g_bucket[(size_t)c * CAP + pos] = make_float4(x, y, z, __int_as_float(j));
        }
    }
    grid_barrier();

    // ---- Phase Q: 16 lanes/point, 16 points/tile, exactly 2 tiles/block ----
    for (int t = tid; t < 2 * DIM * DIM; t += TPB) sW1[t] = W1[t];
    for (int t = tid; t < DIM * DIM; t += TPB)     sW2[t] = W2[t];
    if (tid < DIM) { sb1[tid] = b1[tid]; sb2[tid] = b2[tid]; }
    for (int t = tid; t < BATCH * NCELL; t += TPB) s_cnt[t] = g_cellcnt[t];
    __syncthreads();

    const int lc0 = g_leafcnt[0], lc1 = g_leafcnt[1];
    const int pt = tid >> 4;            // 0..15  local point
    const int ln = tid & 15;            // 0..15  lane within point group
    const unsigned gmask = 0xFFFFu << (tid & 16);    // this group's 16 lanes
    const float* en_i = s_en + pt * PAD;

#pragma unroll
    for (int w = 0; w < 2; w++) {
        const int tile = blockIdx.x + w * NB;
        const int gi0 = tile * PPQ;
        const int b = gi0 >> 13;                         // / NPTS, tile-uniform

        // cooperative stage: tile embeddings (raw + normalized); zero list counters
        for (int t = tid; t < PPQ * DIM; t += TPB) {
            int p = t >> 5, k = t & 31;
            s_ei[p * PAD + k] = __ldg(emb + ((size_t)gi0 + p) * DIM + k);
            s_en[p * PAD + k] = g_en[((size_t)gi0 + p) * DIM + k];
        }
        if (tid < PPQ) s_lcnt[tid] = 0;
        __syncthreads();

        const int gi = gi0 + pt;
        const float xi = __ldg(points + 3 * (size_t)gi);
        const float yi = __ldg(points + 3 * (size_t)gi + 1);
        const float zi = __ldg(points + 3 * (size_t)gi + 2);

        const int cx0 = max(0, (int)((xi - MARGIN) * INVC)), cx1 = min(GRIDC - 1, (int)((xi + MARGIN) * INVC));
        const int cy0 = max(0, (int)((yi - MARGIN) * INVC)), cy1 = min(GRIDC - 1, (int)((yi + MARGIN) * INVC));
        const int cz0 = max(0, (int)((zi - MARGIN) * INVC)), cz1 = min(GRIDC - 1, (int)((zi + MARGIN) * INVC));
        const int nx = cx1 - cx0 + 1, ny = cy1 - cy0 + 1, nz = cz1 - cz0 + 1;
        const int nxy = nx * ny, ncn = nxy * nz;         // <= 64
        const float invnxy = 1.f / (float)nxy;
        const float invnx  = 1.f / (float)nx;

        int nbcnt = 0;
        const float* enb  = g_en + (size_t)b * NPTS * DIM;
        const float* embb = emb  + (size_t)b * NPTS * DIM;
        const int*   cntb = s_cnt + b * NCELL;

#pragma unroll
        for (int s = 0; s < 64 / LPP; s++) {             // 4 iters; lane owns cc
            int cc = ln + s * LPP;
            if (cc < ncn) {
                // division-free decode: exact for cc<64
                int cz = (int)(((float)cc + 0.5f) * invnxy);
                int r  = cc - cz * nxy;
                int cy = (int)(((float)r + 0.5f) * invnx);
                int cx = r - cy * nx;
                int cell = ((cz0 + cz) * GRIDC + (cy0 + cy)) * GRIDC + (cx0 + cx);
                int n = min(cntb[cell], CAP);
                const float4* bk = g_bucket + ((size_t)b * NCELL + cell) * CAP;
                for (int k = 0; k < n; k++) {
                    float4 p = __ldg(bk + k);
                    float dx = xi - p.x, dy = yi - p.y, dz = zi - p.z;
                    float d2 = fmaf(dx, dx, fmaf(dy, dy, dz * dz));
                    if (d2 < R2) {
                        nbcnt++;
                        int j = __float_as_int(p.w);
                        const float4* ej = (const float4*)(enb + (size_t)j * DIM);
                        float dot = 0.f;
#pragma unroll
                        for (int q = 0; q < 8; q++) {
                            float4 v = __ldg(ej + q);
                            float4 u = *(const float4*)(en_i + 4 * q);  // broadcast LDS.128
                            dot = fmaf(v.x, u.x, dot); dot = fmaf(v.y, u.y, dot);
                            dot = fmaf(v.z, u.z, dot); dot = fmaf(v.w, u.w, dot);
                        }
                        if (dot > SIMT) {                // rare: defer j (ONE smem atomic)
                            int pos = atomicAdd(&s_lcnt[pt], 1);
                            if (pos < LCAP) s_list[pt * LCAP + pos] = j;
                        }
                    }
                }
            }
        }

        // 16-lane butterfly reduce of nbcnt (xor d<16 stays within group)
#pragma unroll
        for (int d = 1; d < LPP; d <<= 1)
            nbcnt += __shfl_xor_sync(FULL, nbcnt, d);
        __syncwarp();                                    // list writes visible

        const int cnt = s_lcnt[pt];                      // group-uniform
        const bool cond = (__ldg(leaf + gi) > 0) && (nbcnt > 1) && (cnt > 0)
                       && ((b == 0 ? lc0 : lc1) >= MINLEAF);

        const int ob = ln * 2;
        if (cond) {                                      // group-uniform branch
            const float rinv = 1.f / (float)cnt;         // cnt>0 here: == max(cnt,1)

            // cooperative accumulate: lane owns components {2ln, 2ln+1}
            float acc0 = 0.f, acc1 = 0.f;
            const int mm = min(cnt, LCAP);
            for (int i = 0; i < mm; i++) {
                int jj = s_list[pt * LCAP + i];          // broadcast LDS
                float2 v = *(const float2*)(embb + (size_t)jj * DIM + ob);  // 128B coalesced
                acc0 += v.x; acc1 += v.y;                // RAW embedding (exact)
            }
            const float cA = acc0 * rinv, cB = acc1 * rinv;

            float h0 = sb1[ob], h1 = sb1[ob + 1];
#pragma unroll 8
            for (int k = 0; k < DIM; k++) {
                float c = s_ei[pt * PAD + k];
                float2 wv = *(const float2*)(sW1 + k * DIM + ob);
                h0 = fmaf(c, wv.x, h0); h1 = fmaf(c, wv.y, h1);
            }
            // second half: acc broadcast via width-16 shfl, k ascending (same order)
#pragma unroll 8
            for (int k16 = 0; k16 < 16; k16++) {
                float c0 = __shfl_sync(gmask, cA, k16, 16);   // mean_sim[2*k16]
                float c1 = __shfl_sync(gmask, cB, k16, 16);   // mean_sim[2*k16+1]
                float2 w0 = *(const float2*)(sW1 + (DIM + 2 * k16) * DIM + ob);
                h0 = fmaf(c0, w0.x, h0); h1 = fmaf(c0, w0.y, h1);
                float2 w1 = *(const float2*)(sW1 + (DIM + 2 * k16 + 1) * DIM + ob);
                h0 = fmaf(c1, w1.x, h0); h1 = fmaf(c1, w1.y, h1);
            }
            h0 = fmaxf(h0, 0.f); h1 = fmaxf(h1, 0.f);

            // layer 2: h broadcast via width-16 shfl (group-converged: cond uniform)
            float o0 = sb2[ob], o1 = sb2[ob + 1];
#pragma unroll 8
            for (int k16 = 0; k16 < 16; k16++) {
                float c0 = __shfl_sync(gmask, h0, k16, 16);   // h[2*k16]
                float c1 = __shfl_sync(gmask, h1, k16, 16);   // h[2*k16+1]
                float2 w0 = *(const float2*)(sW2 + (2 * k16) * DIM + ob);
                o0 = fmaf(c0, w0.x, o0); o1 = fmaf(c0, w0.y, o1);
                float2 w1 = *(const float2*)(sW2 + (2 * k16 + 1) * DIM + ob);
                o0 = fmaf(c1, w1.x, o0); o1 = fmaf(c1, w1.y, o1);
            }
            *(float2*)(out + (size_t)gi * DIM + ob) = make_float2(o0, o1);
        } else {
            float2 r = *(const float2*)(s_ei + pt * PAD + ob);   // passthrough
            *(float2*)(out + (size_t)gi * DIM + ob) = r;
        }
        __syncthreads();                                 // before next tile restage
    }
}

extern "C" void kernel_launch(void* const* d_in, const int* in_sizes, int n_in,
                              void* d_out, int out_size) {
    const float* points = (const float*)d_in[0];
    const float* emb    = (const float*)d_in[1];
    const int*   leaf   = (const int*)d_in[2];
    const float* W1     = (const float*)d_in[3];
    const float* b1     = (const float*)d_in[4];
    const float* W2     = (const float*)d_in[5];
    const float* b2     = (const float*)d_in[6];
    float* out = (float*)d_out;

    fused_kernel<<<NB, TPB>>>(points, emb, leaf, W1, b1, W2, b2, out);
}

// round 13
// speedup vs baseline: 1.9946x; 1.2348x over previous
#include <cuda_runtime.h>
#include <cuda_bf16.h>

// Problem constants (fixed by the reference)
#define BATCH   2
#define NPTS    8192
#define NTOT    (BATCH * NPTS)
#define DIM     32
#define R2      0.0009f     // 0.03^2
#define SIMT    0.7f
#define EPSN    1e-8f
#define MINLEAF 10

#define GRIDC   14                      // ceil(0.4 / 0.03)
#define NCELL   (GRIDC * GRIDC * GRIDC) // 2744
#define CAP     32                      // bucket capacity (mean occupancy ~1.5)
#define INVC    33.333332f              // 1 / 0.03
#define MARGIN  0.0302f                 // radius + safety margin for cell-range bound

#define TPB     256
#define NB      512                     // 1024 tiles / 512 blocks = exactly 2 each
#define LPP     16                      // lanes per point
#define PPQ     (TPB / LPP)             // 16 points per tile
#define FULL    0xffffffffu
#define PAD     36                      // smem row pad: 16B-aligned, conflict-safe
#define CCAP    64                      // per-point d2-pass candidate capacity (mean 14.5, sd 3.8)
#define LCAP    32                      // per-point sim-pass list capacity (observed cnt ~1-3)

// Scratch (static __device__ — no allocations allowed)
__device__ float  g_en[NTOT * DIM];                  // normalized embeddings
__device__ int    g_cellcnt[BATCH * NCELL];
__device__ float4 g_bucket[BATCH * NCELL * CAP];     // (x,y,z, bitcast local idx)
__device__ int    g_leafcnt[BATCH];
__device__ int    g_bar_arrive;                      // zero-initialized
__device__ volatile int g_bar_gen;                   // monotonic epoch (never reset)

// Sense-reversal grid barrier. Safe: NB=512 <= 148 SMs x 4 co-resident blocks
// (regs<=64 via launch_bounds(256,4); smem ~45KB*4 <= 228KB).
__device__ __forceinline__ void grid_barrier() {
    __syncthreads();
    if (threadIdx.x == 0) {
        int gen = g_bar_gen;
        __threadfence();
        if (atomicAdd(&g_bar_arrive, 1) == NB - 1) {
            atomicExch(&g_bar_arrive, 0);
            __threadfence();
            g_bar_gen = gen + 1;                     // release
        } else {
            while (g_bar_gen == gen) { __nanosleep(20); }
        }
        __threadfence();
    }
    __syncthreads();
}

__global__ void __launch_bounds__(TPB, 4)
fused_kernel(const float* __restrict__ points,
             const float* __restrict__ emb,
             const int*   __restrict__ leaf,
             const float* __restrict__ W1,
             const float* __restrict__ b1,
             const float* __restrict__ W2,
             const float* __restrict__ b2,
             float* __restrict__ out) {
    __shared__ __align__(16) float sW1[2 * DIM * DIM];   // 8 KB
    __shared__ __align__(16) float sW2[DIM * DIM];       // 4 KB
    __shared__ float sb1[DIM];
    __shared__ float sb2[DIM];
    __shared__ int   s_cnt[BATCH * NCELL];               // 21.4 KB (both batches)
    __shared__ __align__(16) float s_en[PPQ * PAD];      // normalized emb of tile points
    __shared__ __align__(16) float s_ei[PPQ * PAD];      // raw emb of tile points
    __shared__ int   s_cand[PPQ * CCAP];                 // d2-pass candidate lists (4 KB)
    __shared__ int   s_ccnt[PPQ];                        // candidate counters (== nbcnt)
    __shared__ int   s_list[PPQ * LCAP];                 // sim-pass j lists (2 KB)
    __shared__ int   s_lcnt[PPQ];                        // sim-pass counters (== cnt)

    const int tid = threadIdx.x;

    // ---- Phase Z: zero grid state ----
    {
        const int gtid = blockIdx.x * TPB + tid;
        if (gtid < BATCH * NCELL) g_cellcnt[gtid] = 0;
        if (gtid < BATCH)         g_leafcnt[gtid] = 0;
    }
    grid_barrier();

    // ---- Phase P: prep, 32 items per block (16384 = 512*32), 1 item/lane ----
    if (tid < 32) {
        const int idx = blockIdx.x * 32 + tid;           // warp 0 fully active
        const int b = idx / NPTS;                        // warp-homogeneous
        const int j = idx - b * NPTS;

        const float4* e4 = (const float4*)(emb + (size_t)idx * DIM);
        float v[DIM];
        float s = 0.f;
#pragma unroll
        for (int q = 0; q < 8; q++) {
            float4 t = __ldg(e4 + q);
            v[4*q+0] = t.x; v[4*q+1] = t.y; v[4*q+2] = t.z; v[4*q+3] = t.w;
            s = fmaf(t.x, t.x, s); s = fmaf(t.y, t.y, s);
            s = fmaf(t.z, t.z, s); s = fmaf(t.w, t.w, s);
        }
        float inv = 1.f / fmaxf(sqrtf(s), EPSN);
        float4* o4 = (float4*)(g_en + (size_t)idx * DIM);
#pragma unroll
        for (int q = 0; q < 8; q++)
            o4[q] = make_float4(v[4*q] * inv, v[4*q+1] * inv, v[4*q+2] * inv, v[4*q+3] * inv);

        int lf = leaf[idx] > 0;
        unsigned msk = __ballot_sync(FULL, lf);
        if (tid == 0 && msk)
            atomicAdd(&g_leafcnt[b], __popc(msk));

        if (lf) {
            float x = points[3 * (size_t)idx];
            float y = points[3 * (size_t)idx + 1];
            float z = points[3 * (size_t)idx + 2];
            int cx = min(GRIDC - 1, (int)(x * INVC));
            int cy = min(GRIDC - 1, (int)(y * INVC));
            int cz = min(GRIDC - 1, (int)(z * INVC));
            int c = b * NCELL + (cz * GRIDC + cy) * GRIDC + cx;
            int pos = atomicAdd(&g_cellcnt[c], 1);
            if (pos < CAP)
                g_bucket[(size_t)c * CAP + pos] = make_float4(x, y, z, __int_as_float(j));
        }
    }
    grid_barrier();

    // ---- Phase Q: 16 lanes/point, 16 points/tile, exactly 2 tiles/block ----
    for (int t = tid; t < 2 * DIM * DIM; t += TPB) sW1[t] = W1[t];
    for (int t = tid; t < DIM * DIM; t += TPB)     sW2[t] = W2[t];
    if (tid < DIM) { sb1[tid] = b1[tid]; sb2[tid] = b2[tid]; }
    for (int t = tid; t < BATCH * NCELL; t += TPB) s_cnt[t] = g_cellcnt[t];
    __syncthreads();

    const int lc0 = g_leafcnt[0], lc1 = g_leafcnt[1];
    const int pt = tid >> 4;            // 0..15  local point
    const int ln = tid & 15;            // 0..15  lane within point group
    const unsigned gmask = 0xFFFFu << (tid & 16);    // this group's 16 lanes
    const float* en_i = s_en + pt * PAD;

#pragma unroll
    for (int w = 0; w < 2; w++) {
        const int tile = blockIdx.x + w * NB;
        const int gi0 = tile * PPQ;
        const int b = gi0 >> 13;                         // / NPTS, tile-uniform

        // cooperative stage: tile embeddings (raw + normalized); zero counters
        for (int t = tid; t < PPQ * DIM; t += TPB) {
            int p = t >> 5, k = t & 31;
            s_ei[p * PAD + k] = __ldg(emb + ((size_t)gi0 + p) * DIM + k);
            s_en[p * PAD + k] = g_en[((size_t)gi0 + p) * DIM + k];
        }
        if (tid < PPQ) { s_ccnt[tid] = 0; s_lcnt[tid] = 0; }
        __syncthreads();

        const int gi = gi0 + pt;
        const float xi = __ldg(points + 3 * (size_t)gi);
        const float yi = __ldg(points + 3 * (size_t)gi + 1);
        const float zi = __ldg(points + 3 * (size_t)gi + 2);

        const int cx0 = max(0, (int)((xi - MARGIN) * INVC)), cx1 = min(GRIDC - 1, (int)((xi + MARGIN) * INVC));
        const int cy0 = max(0, (int)((yi - MARGIN) * INVC)), cy1 = min(GRIDC - 1, (int)((yi + MARGIN) * INVC));
        const int cz0 = max(0, (int)((zi - MARGIN) * INVC)), cz1 = min(GRIDC - 1, (int)((zi + MARGIN) * INVC));
        const int nx = cx1 - cx0 + 1, ny = cy1 - cy0 + 1, nz = cz1 - cz0 + 1;
        const int nxy = nx * ny, ncn = nxy * nz;         // <= 64
        const float invnxy = 1.f / (float)nxy;
        const float invnx  = 1.f / (float)nx;

        const float* enb  = g_en + (size_t)b * NPTS * DIM;
        const float* embb = emb  + (size_t)b * NPTS * DIM;
        const int*   cntb = s_cnt + b * NCELL;

        // ---- Phase A: geometric scan only; defer passing j to candidate list ----
#pragma unroll
        for (int s = 0; s < 64 / LPP; s++) {             // 4 iters; lane owns cc
            int cc = ln + s * LPP;
            if (cc < ncn) {
                // division-free decode: exact for cc<64
                int cz = (int)(((float)cc + 0.5f) * invnxy);
                int r  = cc - cz * nxy;
                int cy = (int)(((float)r + 0.5f) * invnx);
                int cx = r - cy * nx;
                int cell = ((cz0 + cz) * GRIDC + (cy0 + cy)) * GRIDC + (cx0 + cx);
                int n = min(cntb[cell], CAP);
                const float4* bk = g_bucket + ((size_t)b * NCELL + cell) * CAP;
                for (int k = 0; k < n; k++) {
                    float4 p = __ldg(bk + k);
                    float dx = xi - p.x, dy = yi - p.y, dz = zi - p.z;
                    float d2 = fmaf(dx, dx, fmaf(dy, dy, dz * dz));
                    if (d2 < R2) {                       // tiny divergent region now
                        int pos = atomicAdd(&s_ccnt[pt], 1);
                        if (pos < CCAP) s_cand[pt * CCAP + pos] = __float_as_int(p.w);
                    }
                }
            }
        }
        __syncwarp();                                    // candidate lists visible

        // ---- Phase B: dots computed cooperatively (full SIMT efficiency) ----
        const int nbcnt = s_ccnt[pt];                    // exact count (pre-clamp)
        const int mcand = min(nbcnt, CCAP);
        for (int i = ln; i < mcand; i += LPP) {          // lane takes candidate i
            int j = s_cand[pt * CCAP + i];
            const float4* ej = (const float4*)(enb + (size_t)j * DIM);
            float dot = 0.f;
#pragma unroll
            for (int q = 0; q < 8; q++) {
                float4 v = __ldg(ej + q);
                float4 u = *(const float4*)(en_i + 4 * q);   // broadcast LDS.128
                dot = fmaf(v.x, u.x, dot); dot = fmaf(v.y, u.y, dot);
                dot = fmaf(v.z, u.z, dot); dot = fmaf(v.w, u.w, dot);
            }
            if (dot > SIMT) {                            // rare: defer j
                int pos = atomicAdd(&s_lcnt[pt], 1);
                if (pos < LCAP) s_list[pt * LCAP + pos] = j;
            }
        }
        __syncwarp();                                    // sim lists visible

        const int cnt = s_lcnt[pt];                      // group-uniform
        const bool cond = (__ldg(leaf + gi) > 0) && (nbcnt > 1) && (cnt > 0)
                       && ((b == 0 ? lc0 : lc1) >= MINLEAF);

        const int ob = ln * 2;
        if (cond) {                                      // group-uniform branch
            const float rinv = 1.f / (float)cnt;         // cnt>0 here: == max(cnt,1)

            // cooperative accumulate: lane owns components {2ln, 2ln+1}
            float acc0 = 0.f, acc1 = 0.f;
            const int mm = min(cnt, LCAP);
            for (int i = 0; i < mm; i++) {
                int jj = s_list[pt * LCAP + i];          // broadcast LDS
                float2 v = *(const float2*)(embb + (size_t)jj * DIM + ob);  // 128B coalesced
                acc0 += v.x; acc1 += v.y;                // RAW embedding (exact)
            }
            const float cA = acc0 * rinv, cB = acc1 * rinv;

            float h0 = sb1[ob], h1 = sb1[ob + 1];
#pragma unroll 8
            for (int k = 0; k < DIM; k++) {
                float c = s_ei[pt * PAD + k];
                float2 wv = *(const float2*)(sW1 + k * DIM + ob);
                h0 = fmaf(c, wv.x, h0); h1 = fmaf(c, wv.y, h1);
            }
            // second half: acc broadcast via width-16 shfl, k ascending (same order)
#pragma unroll 8
            for (int k16 = 0; k16 < 16; k16++) {
                float c0 = __shfl_sync(gmask, cA, k16, 16);   // mean_sim[2*k16]
                float c1 = __shfl_sync(gmask, cB, k16, 16);   // mean_sim[2*k16+1]
                float2 w0 = *(const float2*)(sW1 + (DIM + 2 * k16) * DIM + ob);
                h0 = fmaf(c0, w0.x, h0); h1 = fmaf(c0, w0.y, h1);
                float2 w1 = *(const float2*)(sW1 + (DIM + 2 * k16 + 1) * DIM + ob);
                h0 = fmaf(c1, w1.x, h0); h1 = fmaf(c1, w1.y, h1);
            }
            h0 = fmaxf(h0, 0.f); h1 = fmaxf(h1, 0.f);

            // layer 2: h broadcast via width-16 shfl (group-converged: cond uniform)
            float o0 = sb2[ob], o1 = sb2[ob + 1];
#pragma unroll 8
            for (int k16 = 0; k16 < 16; k16++) {
                float c0 = __shfl_sync(gmask, h0, k16, 16);   // h[2*k16]
                float c1 = __shfl_sync(gmask, h1, k16, 16);   // h[2*k16+1]
                float2 w0 = *(const float2*)(sW2 + (2 * k16) * DIM + ob);
                o0 = fmaf(c0, w0.x, o0); o1 = fmaf(c0, w0.y, o1);
                float2 w1 = *(const float2*)(sW2 + (2 * k16 + 1) * DIM + ob);
                o0 = fmaf(c1, w1.x, o0); o1 = fmaf(c1, w1.y, o1);
            }
            *(float2*)(out + (size_t)gi * DIM + ob) = make_float2(o0, o1);
        } else {
            float2 r = *(const float2*)(s_ei + pt * PAD + ob);   // passthrough
            *(float2*)(out + (size_t)gi * DIM + ob) = r;
        }
        __syncthreads();                                 // before next tile restage
    }
}

extern "C" void kernel_launch(void* const* d_in, const int* in_sizes, int n_in,
                              void* d_out, int out_size) {
    const float* points = (const float*)d_in[0];
    const float* emb    = (const float*)d_in[1];
    const int*   leaf   = (const int*)d_in[2];
    const float* W1     = (const float*)d_in[3];
    const float* b1     = (const float*)d_in[4];
    const float* W2     = (const float*)d_in[5];
    const float* b2     = (const float*)d_in[6];
    float* out = (float*)d_out;

    fused_kernel<<<NB, TPB>>>(points, emb, leaf, W1, b1, W2, b2, out);
}